// round 9
// baseline (speedup 1.0000x reference)
#include <cuda_runtime.h>
#include <math.h>

#define HIDDEN 1024
#define NINTER 256
#define WINDOW 64
#define FIX_SCALE 281474976710656.0   // 2^48

// persistent state (allocation-free rule: __device__ globals)
// g_fix/g_ticket are monotonic across replays; per-replay values are recovered
// by exact modular difference / mod-256 ticket -> no reset node required.
__device__ unsigned long long g_fix;    // fixed-point sum of tanh terms
__device__ unsigned long long g_base;   // snapshot of g_fix at last replay end
__device__ unsigned           g_ticket;
__device__ int4               g_head;   // {ws, we, et_bits, 0}

// fp64 exp, rel err ~1e-13 (range reduction + degree-9, Estrin form)
__device__ __forceinline__ double fast_exp(double x) {
    const double LOG2E  = 1.4426950408889634074;
    const double LN2_HI = 6.9314718055994528623e-1;
    const double LN2_LO = 2.3190468138462995584e-17;
    double n = rint(x * LOG2E);
    double r = fma(-n, LN2_HI, x);
    r = fma(-n, LN2_LO, r);
    double p01 = 1.0 + r;
    double p23 = fma(r, 1.6666666666666665741e-1, 5.0e-1);
    double p45 = fma(r, 8.3333333333333332177e-3, 4.1666666666666664354e-2);
    double p67 = fma(r, 1.9841269841269841253e-4, 1.3888888888888889419e-3);
    double p89 = fma(r, 2.7557319223985890653e-6, 2.4801587301587301566e-5);
    double r2 = r * r;
    double q0 = fma(r2, p23, p01);
    double q1 = fma(r2, p67, p45);
    double r4 = r2 * r2;
    double s0 = fma(r4, q1, q0);
    double r8 = r4 * r4;
    double res = fma(r8, p89, s0);
    long long ni = (long long)n;
    double sc = __longlong_as_double((ni + 1023LL) << 52);  // exact 2^n
    return res * sc;
}

// 1/d via fp32 rcp seed + 1 fp64 Newton step (rel err ~2^-44)
__device__ __forceinline__ double fast_recip(double d) {
    double y = (double)__frcp_rn((float)d);
    return y * fma(-d, y, 2.0);
}

// ---------------------------------------------------------------------------
// Kernel 1: block-per-row MLP. Each block folds tanhf(z_row)*fc2_w[row] into
// the fixed-point atomic sum; the LAST block (mod-256 ticket) computes the
// exact head (p_t, window, e_t) and publishes g_head. PDL launch_dependents
// fires immediately so K2 rolls out concurrently.
// ---------------------------------------------------------------------------
__global__ void __launch_bounds__(256) mlp1_kernel(
        const float* __restrict__ ht,
        const float* __restrict__ fc1_w,
        const float* __restrict__ fc1_b,
        const float* __restrict__ fc2_w,
        const float* __restrict__ fc2_b, int S) {
    asm volatile("griddepcontrol.launch_dependents;" ::: "memory");

    const int tid  = threadIdx.x;
    const int lane = tid & 31;
    const int wid  = tid >> 5;
    const int bid  = blockIdx.x;

    float4 w = ((const float4*)(fc1_w + (size_t)bid * HIDDEN))[tid];
    float4 h = ((const float4*)ht)[tid];
    // fp64 per-thread dot (exact-ish), then cheap fp32 reduction
    double e0 = fma((double)w.y, (double)h.y, (double)w.x * h.x);
    double e1 = fma((double)w.w, (double)h.w, (double)w.z * h.z);
    float accf = (float)(e0 + e1);
    #pragma unroll
    for (int o = 16; o > 0; o >>= 1)
        accf += __shfl_down_sync(0xffffffffu, accf, o);

    __shared__ float s[8];
    if (lane == 0) s[wid] = accf;
    __syncthreads();

    if (tid == 0) {
        float zf = ((s[0] + s[1]) + (s[2] + s[3]))
                 + ((s[4] + s[5]) + (s[6] + s[7]))
                 + fc1_b[bid];
        float term = tanhf(zf) * fc2_w[bid];
        // exact fixed-point contribution (x * 2^48 is exact in fp32)
        long long fx = __float2ll_rn(term * (float)FIX_SCALE);
        atomicAdd(&g_fix, (unsigned long long)fx);
        __threadfence();
        unsigned t = atomicAdd(&g_ticket, 1u);
        if (((t + 1u) & 255u) == 0u) {          // last block of this replay
            unsigned long long cur  = atomicAdd(&g_fix, 0ULL);
            unsigned long long prev = atomicExch(&g_base, cur);
            long long diff = (long long)(cur - prev);   // exact modular diff
            double z  = (double)diff * (1.0 / FIX_SCALE) + (double)fc2_b[0];
            double e  = fast_exp(-z);
            double pt = (double)S * fast_recip(1.0 + e);
            // pt in (0,S), non-integer: ceil(pt-64)=floor(pt)-63,
            //                           floor(pt+64)=floor(pt)+64
            int k  = (int)pt;
            int ws = k - (WINDOW - 1);  if (ws < 0)     ws = 0;
            int we = k + WINDOW;        if (we > S - 1) we = S - 1;
            float et = __expf((float)(((double)S - pt) * (1.0 / 2048.0)));
            g_head = make_int4(ws, we, __float_as_int(et), 0);
        }
    }
}

// ---------------------------------------------------------------------------
// Kernel 2 (PDL dependent): minimal post-wait chain.
//   wait -> 16B g_head load -> <=3 predicated window loads -> fp32 shuffle +
//   smem reduce -> scale by e_t -> store. No fp64, no head math.
// ---------------------------------------------------------------------------
__global__ void __launch_bounds__(256) windowsum_kernel(
        const float* __restrict__ hs,
        float* __restrict__ out) {
    const int tid  = threadIdx.x;
    const int lane = tid & 31;
    const int wid  = tid >> 5;

    __shared__ float colsum[8][36];

    // prologue independent of K1 (overlaps K1 under PDL)
    const int col    = (blockIdx.x << 2) + (tid & 3);
    const int rowoff = tid >> 2;                     // 0..63
    const float* base = hs + col;

    asm volatile("griddepcontrol.wait;" ::: "memory");

    const int4 hd = __ldcg(&g_head);
    const int   ws = hd.x;
    const int   we = hd.y;
    const float et = __int_as_float(hd.z);

    const int r0 = ws + rowoff;
    const int r1 = r0 + 64;
    const int r2 = r0 + 128;

    float acc = 0.f;
    if (r0 <= we) acc += base[(size_t)r0 * HIDDEN];
    if (r1 <= we) acc += base[(size_t)r1 * HIDDEN];
    if (r2 <= we) acc += base[(size_t)r2 * HIDDEN];

    // fold the 8 rowgroups within each warp (keeps the 4 column lanes)
    #pragma unroll
    for (int o = 16; o >= 4; o >>= 1)
        acc += __shfl_xor_sync(0xffffffffu, acc, o);
    if (lane < 4) colsum[wid][lane] = acc;           // 8 warps x 4 cols
    __syncthreads();

    if (tid < 4) {
        float s = ((colsum[0][tid] + colsum[1][tid])
                 + (colsum[2][tid] + colsum[3][tid]))
                + ((colsum[4][tid] + colsum[5][tid])
                 + (colsum[6][tid] + colsum[7][tid]));
        out[col] = et * s;
    }
}

extern "C" void kernel_launch(void* const* d_in, const int* in_sizes, int n_in,
                              void* d_out, int out_size) {
    const float* hs    = (const float*)d_in[0];
    const float* ht    = (const float*)d_in[1];
    const float* fc1_w = (const float*)d_in[2];
    const float* fc1_b = (const float*)d_in[3];
    const float* fc2_w = (const float*)d_in[4];
    const float* fc2_b = (const float*)d_in[5];

    const int S = in_sizes[0] / HIDDEN;   // host-side constant, capture-safe

    mlp1_kernel<<<NINTER, 256>>>(ht, fc1_w, fc1_b, fc2_w, fc2_b, S);

    // K2 as a PDL dependent launch
    cudaLaunchConfig_t cfg = {};
    cfg.gridDim  = dim3(NINTER, 1, 1);
    cfg.blockDim = dim3(256, 1, 1);
    cfg.dynamicSmemBytes = 0;
    cfg.stream = 0;
    cudaLaunchAttribute attr[1];
    attr[0].id = cudaLaunchAttributeProgrammaticStreamSerialization;
    attr[0].val.programmaticStreamSerializationAllowed = 1;
    cfg.attrs = attr;
    cfg.numAttrs = 1;
    float* outp = (float*)d_out;
    cudaLaunchKernelEx(&cfg, windowsum_kernel, hs, outp);
}